// round 15
// baseline (speedup 1.0000x reference)
#include <cuda_runtime.h>
#include <cuda_bf16.h>
#include <cuda_fp16.h>
#include <cstdint>

#define NB 4
#define NT 4096
#define NE 1024
#define HS 64

// Scratch (static device arrays — no allocation)
__device__ float    g_q[NB * NT * HS];
__device__ uint32_t g_kh[NB * NT * 32];      // K fp16x2 pairs along d
__device__ uint32_t g_vth[NB * HS * 2048];   // V^T fp16x2, [b][d][t-pairs]
__device__ uint32_t g_whp[192 * 512];        // W split hi (bf16, for qkv)
__device__ uint32_t g_wlp[192 * 512];        // W split lo

// ---------------------------------------------------------------------------
__device__ __forceinline__ void split2(float a, float b, uint32_t& hi, uint32_t& lo) {
    __nv_bfloat162 h2 = __floats2bfloat162_rn(a, b);
    float2 hf = __bfloat1622float2(h2);
    __nv_bfloat162 l2 = __floats2bfloat162_rn(a - hf.x, b - hf.y);
    hi = *reinterpret_cast<uint32_t*>(&h2);
    lo = *reinterpret_cast<uint32_t*>(&l2);
}

__device__ __forceinline__ uint32_t h2pack(float a, float b) {
    __half2 h = __floats2half2_rn(a, b);
    return *reinterpret_cast<uint32_t*>(&h);
}

// bf16 MMA (qkv)
__device__ __forceinline__ void mma16816(float* c, const uint32_t* a,
                                         uint32_t b0, uint32_t b1) {
    asm volatile(
        "mma.sync.aligned.m16n8k16.row.col.f32.bf16.bf16.f32 "
        "{%0,%1,%2,%3}, {%4,%5,%6,%7}, {%8,%9}, {%0,%1,%2,%3};"
        : "+f"(c[0]), "+f"(c[1]), "+f"(c[2]), "+f"(c[3])
        : "r"(a[0]), "r"(a[1]), "r"(a[2]), "r"(a[3]), "r"(b0), "r"(b1));
}

// fp16 MMA (attention)
__device__ __forceinline__ void mma16816h(float* c, const uint32_t* a,
                                          uint32_t b0, uint32_t b1) {
    asm volatile(
        "mma.sync.aligned.m16n8k16.row.col.f32.f16.f16.f32 "
        "{%0,%1,%2,%3}, {%4,%5,%6,%7}, {%8,%9}, {%0,%1,%2,%3};"
        : "+f"(c[0]), "+f"(c[1]), "+f"(c[2]), "+f"(c[3])
        : "r"(a[0]), "r"(a[1]), "r"(a[2]), "r"(a[3]), "r"(b0), "r"(b1));
}

__device__ __forceinline__ void ldsm4(uint32_t* r, uint32_t addr) {
    asm volatile("ldmatrix.sync.aligned.m8n8.x4.shared.b16 {%0,%1,%2,%3}, [%4];"
                 : "=r"(r[0]), "=r"(r[1]), "=r"(r[2]), "=r"(r[3]) : "r"(addr));
}

__device__ __forceinline__ uint32_t smem_u32(const void* p) {
    uint32_t a;
    asm("{ .reg .u64 t; cvta.to.shared.u64 t, %1; cvt.u32.u64 %0, t; }"
        : "=r"(a) : "l"(p));
    return a;
}

__device__ __forceinline__ void cp16(uint32_t s, const void* g) {
    asm volatile("cp.async.cg.shared.global [%0], [%1], 16;"
                 :: "r"(s), "l"(__cvta_generic_to_global(g)) : "memory");
}

#define ROWB 144   // padded smem row stride — conflict-free ldmatrix

// ===========================================================================
// Stage 0: one-time W split (bf16 hi/lo for the qkv GEMM)
// ===========================================================================
__global__ __launch_bounds__(256) void wprep(
    const float* __restrict__ Wq,
    const float* __restrict__ Wk,
    const float* __restrict__ Wv)
{
    const int row = blockIdx.x;
    const float* W = (row < 64) ? Wq : ((row < 128) ? Wk : Wv);
    const int r = row & 63;
    #pragma unroll
    for (int i = 0; i < 2; i++) {
        const int p = threadIdx.x + i * 256;
        float2 v = *(const float2*)&W[(size_t)r * NE + 2 * p];
        uint32_t hi, lo;
        split2(v.x, v.y, hi, lo);
        g_whp[row * 512 + p] = hi;
        g_wlp[row * 512 + p] = lo;
    }
}

// ===========================================================================
// Stage 1: fused QKV projection (split bf16, 3 passes — precision required).
// Writes Q fp32, K fp16, V^T fp16.
// ===========================================================================
#define QKV_XH 0
#define QKV_XL 18432
#define QKV_WBASE 36864
#define QKV_WSTG 55296
#define QKV_SMEM (QKV_WBASE + 3 * QKV_WSTG)   // 202752

__global__ __launch_bounds__(256, 1) void qkv_mma(
    const float* __restrict__ x,
    const float* __restrict__ Wq,
    const float* __restrict__ Wk,
    const float* __restrict__ Wv)
{
    extern __shared__ __align__(16) char sm[];
    const uint32_t sb = smem_u32(sm);
    char* Xh = sm + QKV_XH;
    char* Xl = sm + QKV_XL;

    const int tid = threadIdx.x;
    const int wid = tid >> 5;
    const int lane = tid & 31;
    const int g  = lane >> 2;
    const int t3 = lane & 3;
    const int m8 = lane >> 3;
    const int r8 = lane & 7;
    const int rowblk = blockIdx.x * 128;

    const uint32_t lmw = (uint32_t)(((m8 >> 1) * 8 + r8) * ROWB + (m8 & 1) * 16);

    const int xrow = tid >> 1;
    const int xc0  = (tid & 1) * 32;
    const int xob  = xrow * ROWB + xc0 * 2;

    float c[24][4];
    #pragma unroll
    for (int nt = 0; nt < 24; nt++)
        #pragma unroll
        for (int i = 0; i < 4; i++) c[nt][i] = 0.f;

    float4 xr[8];
    {
        const float4* xsrc = (const float4*)&x[(size_t)(rowblk + xrow) * NE + xc0];
        #pragma unroll
        for (int i = 0; i < 8; i++) xr[i] = xsrc[i];
    }

    #pragma unroll
    for (int pc = 0; pc < 2; pc++) {
        const uint32_t wst = sb + QKV_WBASE + pc * QKV_WSTG;
        #pragma unroll
        for (int i = 0; i < 6; i++) {
            const int idx = tid + i * 256;
            const int row = idx >> 3;
            const int off = (idx & 7) * 16;
            cp16(wst + row * ROWB + off,         (const char*)g_whp + row * 2048 + pc * 128 + off);
            cp16(wst + 27648 + row * ROWB + off, (const char*)g_wlp + row * 2048 + pc * 128 + off);
        }
        asm volatile("cp.async.commit_group;" ::: "memory");
    }

    int stg = 0;
    for (int kci = 0; kci < 16; kci++) {
        if (kci < 15)
            asm volatile("cp.async.wait_group 1;" ::: "memory");
        else
            asm volatile("cp.async.wait_group 0;" ::: "memory");
        __syncthreads();

        if (kci + 2 < 16) {
            const int ps = stg + 2 >= 3 ? stg - 1 : stg + 2;
            const uint32_t wst = sb + QKV_WBASE + ps * QKV_WSTG;
            const int kb2 = (kci + 2) * 128;
            #pragma unroll
            for (int i = 0; i < 6; i++) {
                const int idx = tid + i * 256;
                const int row = idx >> 3;
                const int off = (idx & 7) * 16;
                cp16(wst + row * ROWB + off,         (const char*)g_whp + row * 2048 + kb2 + off);
                cp16(wst + 27648 + row * ROWB + off, (const char*)g_wlp + row * 2048 + kb2 + off);
            }
            asm volatile("cp.async.commit_group;" ::: "memory");
        }

        {
            uint32_t hp[16], lp[16];
            #pragma unroll
            for (int i = 0; i < 8; i++) {
                split2(xr[i].x, xr[i].y, hp[2*i],   lp[2*i]);
                split2(xr[i].z, xr[i].w, hp[2*i+1], lp[2*i+1]);
            }
            #pragma unroll
            for (int i = 0; i < 4; i++) {
                *(uint4*)(Xh + xob + 16*i) = make_uint4(hp[4*i], hp[4*i+1], hp[4*i+2], hp[4*i+3]);
                *(uint4*)(Xl + xob + 16*i) = make_uint4(lp[4*i], lp[4*i+1], lp[4*i+2], lp[4*i+3]);
            }
        }
        __syncwarp();

        if (kci + 1 < 16) {
            const float4* xsrc = (const float4*)&x[(size_t)(rowblk + xrow) * NE + (kci + 1) * 64 + xc0];
            #pragma unroll
            for (int i = 0; i < 8; i++) xr[i] = xsrc[i];
        }

        const uint32_t whb = sb + QKV_WBASE + stg * QKV_WSTG;
        const uint32_t wlb = whb + 27648;

        const int rb = (wid * 16 + g) * ROWB;
        #pragma unroll
        for (int ks = 0; ks < 4; ks++) {
            const int colb = ks * 32 + t3 * 4;
            uint32_t ah[4], al[4];
            ah[0] = *(uint32_t*)(Xh + rb + colb);
            ah[1] = *(uint32_t*)(Xh + rb + 8*ROWB + colb);
            ah[2] = *(uint32_t*)(Xh + rb + colb + 16);
            ah[3] = *(uint32_t*)(Xh + rb + 8*ROWB + colb + 16);
            al[0] = *(uint32_t*)(Xl + rb + colb);
            al[1] = *(uint32_t*)(Xl + rb + 8*ROWB + colb);
            al[2] = *(uint32_t*)(Xl + rb + colb + 16);
            al[3] = *(uint32_t*)(Xl + rb + 8*ROWB + colb + 16);
            #pragma unroll
            for (int ntp = 0; ntp < 12; ntp++) {
                uint32_t wh4[4], wl4[4];
                ldsm4(wh4, whb + lmw + ntp * (16 * ROWB) + ks * 32);
                ldsm4(wl4, wlb + lmw + ntp * (16 * ROWB) + ks * 32);
                mma16816(c[2*ntp],   ah, wh4[0], wh4[1]);
                mma16816(c[2*ntp],   ah, wl4[0], wl4[1]);
                mma16816(c[2*ntp],   al, wh4[0], wh4[1]);
                mma16816(c[2*ntp+1], ah, wh4[2], wh4[3]);
                mma16816(c[2*ntp+1], ah, wl4[2], wl4[3]);
                mma16816(c[2*ntp+1], al, wh4[2], wh4[3]);
            }
        }
        stg = (stg + 1 == 3) ? 0 : stg + 1;
    }

    const int r0 = rowblk + wid * 16 + g;
    // Q: fp32 (converted to fp16 inside attn after 1/8 scaling)
    #pragma unroll
    for (int nt = 0; nt < 8; nt++) {
        const int col = nt * 8 + t3 * 2;
        *(float2*)&g_q[(size_t)r0 * HS + col]       = make_float2(c[nt][0], c[nt][1]);
        *(float2*)&g_q[(size_t)(r0 + 8) * HS + col] = make_float2(c[nt][2], c[nt][3]);
    }
    // K: fp16 pairs along d
    #pragma unroll
    for (int nt = 8; nt < 16; nt++) {
        const int pidx = (nt - 8) * 4 + t3;
        g_kh[(size_t)r0 * 32 + pidx]       = h2pack(c[nt][0], c[nt][1]);
        g_kh[(size_t)(r0 + 8) * 32 + pidx] = h2pack(c[nt][2], c[nt][3]);
    }

    // V: stage fp32 to smem, write transposed fp16
    __syncthreads();
    float* Vs = (float*)sm;
    const int rloc = wid * 16 + g;
    #pragma unroll
    for (int nt = 16; nt < 24; nt++) {
        const int n = nt * 8 + t3 * 2 - 128;
        Vs[n * 132 + rloc]           = c[nt][0];
        Vs[(n + 1) * 132 + rloc]     = c[nt][1];
        Vs[n * 132 + rloc + 8]       = c[nt][2];
        Vs[(n + 1) * 132 + rloc + 8] = c[nt][3];
    }
    __syncthreads();
    {
        const int d  = tid >> 2;
        const int cc = (tid & 3) * 32;
        const int bb = rowblk >> 12;
        const int t0 = rowblk & (NT - 1);
        uint32_t* dh = &g_vth[((size_t)(bb * HS + d)) * 2048 + (t0 + cc) / 2];
        #pragma unroll
        for (int i = 0; i < 8; i++) {
            float4 v = *(float4*)&Vs[d * 132 + cc + 4*i];
            dh[2*i]   = h2pack(v.x, v.y);
            dh[2*i+1] = h2pack(v.z, v.w);
        }
    }
}

// ===========================================================================
// Stage 2: causal flash attention, single-pass fp16 HMMA.
// 64-key tiles, 3-stage ring, warps 0-3 keys 0-31 / 4-7 keys 32-63.
// ===========================================================================
#define ATSTG 18432                 // stage: KH 9216 | VH 9216
#define AT_QHO (3 * ATSTG)          // 55296
#define AT_MSO (AT_QHO + 9216)      // 64512, float2[2][64]
#define AT_SMEM (AT_MSO + 1024)     // 65536
#define OEXW 66

__global__ __launch_bounds__(256, 1) void attn5(float* __restrict__ o)
{
    extern __shared__ __align__(16) char sm[];
    const uint32_t sb = smem_u32(sm);
    const int tid  = threadIdx.x;
    const int lane = tid & 31;
    const int g    = lane >> 2;
    const int t3   = lane & 3;
    const int wq   = (tid >> 5) & 3;
    const int side = tid >> 7;
    const int b    = blockIdx.y;

    const int m8 = lane >> 3;
    const int r8 = lane & 7;
    const uint32_t lmk = (uint32_t)((side * 32 + (m8 >> 1) * 8 + r8) * ROWB + (m8 & 1) * 16);
    const uint32_t lmv = (uint32_t)(((m8 >> 1) * 8 + r8) * ROWB + (m8 & 1) * 16 + side * 64);

    const char* khg = (const char*)g_kh + (size_t)b * NT * 128;
    const char* vhg = (const char*)g_vth + (size_t)b * HS * 8192;

    const int pc_row = (tid * 2) >> 3;
    const int pc_off = ((tid * 2) & 7) * 16;

    for (int half = 0; half < 2; half++) {
        const int qt = half ? (63 - (int)blockIdx.x) : (int)blockIdx.x;
        const int nkt = qt + 1;
        const int qrow = b * NT + qt * 64;

        __syncthreads();   // prior half done (epilogue reads + cp drained)

        // ---- stage Q (scaled 1/8, fp16) ----
        {
            const int r  = tid >> 2;
            const int c0 = (tid & 3) * 16;
            const float4* src = (const float4*)&g_q[(size_t)(qrow + r) * HS + c0];
            uint32_t hp[8];
            #pragma unroll
            for (int i = 0; i < 4; i++) {
                float4 v = src[i];
                hp[2*i]   = h2pack(v.x * 0.125f, v.y * 0.125f);
                hp[2*i+1] = h2pack(v.z * 0.125f, v.w * 0.125f);
            }
            const int ob = r * ROWB + c0 * 2;
            *(uint4*)(sm + AT_QHO + ob)      = make_uint4(hp[0], hp[1], hp[2], hp[3]);
            *(uint4*)(sm + AT_QHO + ob + 16) = make_uint4(hp[4], hp[5], hp[6], hp[7]);
        }
        __syncthreads();

        // ---- preload Q fragments ----
        uint32_t qh[4][4];
        {
            const int rb = (wq * 16 + g) * ROWB;
            #pragma unroll
            for (int ks = 0; ks < 4; ks++) {
                const int colb = ks * 32 + t3 * 4;
                qh[ks][0] = *(uint32_t*)(sm + AT_QHO + rb + colb);
                qh[ks][1] = *(uint32_t*)(sm + AT_QHO + rb + 8*ROWB + colb);
                qh[ks][2] = *(uint32_t*)(sm + AT_QHO + rb + colb + 16);
                qh[ks][3] = *(uint32_t*)(sm + AT_QHO + rb + 8*ROWB + colb + 16);
            }
        }

        float oacc[8][4];
        #pragma unroll
        for (int nt = 0; nt < 8; nt++)
            #pragma unroll
            for (int i = 0; i < 4; i++) oacc[nt][i] = 0.f;
        float mi0 = -1e30f, mi1 = -1e30f, li0 = 0.f, li1 = 0.f;

        // ---- prefetch tiles 0 and 1 ----
        #pragma unroll 1
        for (int pt = 0; pt < 2; pt++) {
            if (pt < nkt) {
                const uint32_t so = sb + pt * ATSTG + pc_row * ROWB + pc_off;
                const size_t ko = (size_t)(pt * 64 + pc_row) * 128 + pc_off;
                const size_t vo = (size_t)pc_row * 8192 + pt * 128 + pc_off;
                cp16(so,        khg + ko);  cp16(so + 16,        khg + ko + 16);
                cp16(so + 9216, vhg + vo);  cp16(so + 9216 + 16, vhg + vo + 16);
                asm volatile("cp.async.commit_group;" ::: "memory");
            }
        }

        int stg = 0;
        for (int kt = 0; kt < nkt; kt++) {
            if (kt + 1 < nkt)
                asm volatile("cp.async.wait_group 1;" ::: "memory");
            else
                asm volatile("cp.async.wait_group 0;" ::: "memory");
            __syncthreads();   // [A] stage visible; stage (stg+2)%3 drained

            if (kt + 2 < nkt) {
                const int ps = stg + 2 >= 3 ? stg - 1 : stg + 2;
                const int t2 = kt + 2;
                const uint32_t so = sb + ps * ATSTG + pc_row * ROWB + pc_off;
                const size_t ko = (size_t)(t2 * 64 + pc_row) * 128 + pc_off;
                const size_t vo = (size_t)pc_row * 8192 + t2 * 128 + pc_off;
                cp16(so,        khg + ko);  cp16(so + 16,        khg + ko + 16);
                cp16(so + 9216, vhg + vo);  cp16(so + 9216 + 16, vhg + vo + 16);
                asm volatile("cp.async.commit_group;" ::: "memory");
            }

            const uint32_t khb = sb + stg * ATSTG;
            const uint32_t vhb = khb + 9216;

            // ---- S = Q K^T (warp's 32 keys, single fp16 pass) ----
            float s[4][4];
            #pragma unroll
            for (int nt = 0; nt < 4; nt++)
                #pragma unroll
                for (int i = 0; i < 4; i++) s[nt][i] = 0.f;
            #pragma unroll
            for (int ks = 0; ks < 4; ks++) {
                uint32_t a4[4], b4[4];
                ldsm4(a4, khb + lmk + ks * 32);
                ldsm4(b4, khb + lmk + 16 * ROWB + ks * 32);
                mma16816h(s[0], qh[ks], a4[0], a4[1]);
                mma16816h(s[1], qh[ks], a4[2], a4[3]);
                mma16816h(s[2], qh[ks], b4[0], b4[1]);
                mma16816h(s[3], qh[ks], b4[2], b4[3]);
            }

            if (kt == qt) {
                const int lr0 = wq * 16 + g;
                #pragma unroll
                for (int nt = 0; nt < 4; nt++) {
                    const int lc = side * 32 + nt * 8 + t3 * 2;
                    if (lc > lr0)         s[nt][0] = -1e30f;
                    if (lc + 1 > lr0)     s[nt][1] = -1e30f;
                    if (lc > lr0 + 8)     s[nt][2] = -1e30f;
                    if (lc + 1 > lr0 + 8) s[nt][3] = -1e30f;
                }
            }

            // ---- partial softmax over warp's 32 cols ----
            float m0 = -1e30f, m1 = -1e30f;
            #pragma unroll
            for (int nt = 0; nt < 4; nt++) {
                m0 = fmaxf(m0, fmaxf(s[nt][0], s[nt][1]));
                m1 = fmaxf(m1, fmaxf(s[nt][2], s[nt][3]));
            }
            m0 = fmaxf(m0, __shfl_xor_sync(0xffffffffu, m0, 1));
            m0 = fmaxf(m0, __shfl_xor_sync(0xffffffffu, m0, 2));
            m1 = fmaxf(m1, __shfl_xor_sync(0xffffffffu, m1, 1));
            m1 = fmaxf(m1, __shfl_xor_sync(0xffffffffu, m1, 2));

            float sum0 = 0.f, sum1 = 0.f;
            #pragma unroll
            for (int nt = 0; nt < 4; nt++) {
                s[nt][0] = __expf(s[nt][0] - m0);
                s[nt][1] = __expf(s[nt][1] - m0);
                s[nt][2] = __expf(s[nt][2] - m1);
                s[nt][3] = __expf(s[nt][3] - m1);
                sum0 += s[nt][0] + s[nt][1];
                sum1 += s[nt][2] + s[nt][3];
            }
            sum0 += __shfl_xor_sync(0xffffffffu, sum0, 1);
            sum0 += __shfl_xor_sync(0xffffffffu, sum0, 2);
            sum1 += __shfl_xor_sync(0xffffffffu, sum1, 1);
            sum1 += __shfl_xor_sync(0xffffffffu, sum1, 2);

            // ---- exchange (max, sum) with partner warp ----
            if (t3 == 0) {
                *(float2*)(sm + AT_MSO + (side * 64 + wq * 16 + g) * 8)     = make_float2(m0, sum0);
                *(float2*)(sm + AT_MSO + (side * 64 + wq * 16 + g + 8) * 8) = make_float2(m1, sum1);
            }
            asm volatile("bar.sync %0, 64;" :: "r"(1 + wq) : "memory");
            const float2 ot0 = *(float2*)(sm + AT_MSO + ((1 - side) * 64 + wq * 16 + g) * 8);
            const float2 ot1 = *(float2*)(sm + AT_MSO + ((1 - side) * 64 + wq * 16 + g + 8) * 8);

            const float mn0 = fmaxf(mi0, fmaxf(m0, ot0.x));
            const float mn1 = fmaxf(mi1, fmaxf(m1, ot1.x));
            const float fo0 = __expf(m0 - mn0), fo1 = __expf(m1 - mn1);
            const float corr0 = __expf(mi0 - mn0), corr1 = __expf(mi1 - mn1);
            li0 = li0 * corr0 + sum0 * fo0 + ot0.y * __expf(ot0.x - mn0);
            li1 = li1 * corr1 + sum1 * fo1 + ot1.y * __expf(ot1.x - mn1);
            mi0 = mn0;  mi1 = mn1;

            #pragma unroll
            for (int nt = 0; nt < 4; nt++) {
                s[nt][0] *= fo0;  s[nt][1] *= fo0;
                s[nt][2] *= fo1;  s[nt][3] *= fo1;
            }
            #pragma unroll
            for (int nt = 0; nt < 8; nt++) {
                oacc[nt][0] *= corr0;  oacc[nt][1] *= corr0;
                oacc[nt][2] *= corr1;  oacc[nt][3] *= corr1;
            }

            // ---- O += P V (fp16 P, fp16 V, single pass) ----
            #pragma unroll
            for (int k2 = 0; k2 < 2; k2++) {
                uint32_t pah[4];
                pah[0] = h2pack(s[2*k2][0],   s[2*k2][1]);
                pah[1] = h2pack(s[2*k2][2],   s[2*k2][3]);
                pah[2] = h2pack(s[2*k2+1][0], s[2*k2+1][1]);
                pah[3] = h2pack(s[2*k2+1][2], s[2*k2+1][3]);
                #pragma unroll
                for (int dt = 0; dt < 4; dt++) {
                    uint32_t vh4[4];
                    ldsm4(vh4, vhb + dt * (16 * ROWB) + lmv + k2 * 32);
                    mma16816h(oacc[2*dt],   pah, vh4[0], vh4[1]);
                    mma16816h(oacc[2*dt+1], pah, vh4[2], vh4[3]);
                }
            }
            stg = (stg + 1 == 3) ? 0 : stg + 1;
        }

        // ---- epilogue: merge O partials ----
        __syncthreads();
        float* Oex = (float*)sm;   // stage 0 area, pipeline drained
        if (side == 1) {
            #pragma unroll
            for (int nt = 0; nt < 8; nt++) {
                const int col = nt * 8 + t3 * 2;
                Oex[(wq*16 + g) * OEXW + col]         = oacc[nt][0];
                Oex[(wq*16 + g) * OEXW + col + 1]     = oacc[nt][1];
                Oex[(wq*16 + g + 8) * OEXW + col]     = oacc[nt][2];
                Oex[(wq*16 + g + 8) * OEXW + col + 1] = oacc[nt][3];
            }
        }
        __syncthreads();
        if (side == 0) {
            const float inv0 = 1.0f / li0;
            const float inv1 = 1.0f / li1;
            const int rowA = qrow + wq * 16 + g;
            #pragma unroll
            for (int nt = 0; nt < 8; nt++) {
                const int col = nt * 8 + t3 * 2;
                float a0 = (oacc[nt][0] + Oex[(wq*16 + g) * OEXW + col])     * inv0;
                float a1 = (oacc[nt][1] + Oex[(wq*16 + g) * OEXW + col + 1]) * inv0;
                float a2 = (oacc[nt][2] + Oex[(wq*16 + g + 8) * OEXW + col])     * inv1;
                float a3 = (oacc[nt][3] + Oex[(wq*16 + g + 8) * OEXW + col + 1]) * inv1;
                *(float2*)&o[(size_t)rowA * HS + col]       = make_float2(a0, a1);
                *(float2*)&o[(size_t)(rowA + 8) * HS + col] = make_float2(a2, a3);
            }
        }
    }
}

// ===========================================================================
extern "C" void kernel_launch(void* const* d_in, const int* in_sizes, int n_in,
                              void* d_out, int out_size)
{
    const float* x  = (const float*)d_in[0];
    const float* Wq = (const float*)d_in[1];
    const float* Wk = (const float*)d_in[2];
    const float* Wv = (const float*)d_in[3];
    float* out = (float*)d_out;
    (void)in_sizes; (void)n_in; (void)out_size;

    wprep<<<192, 256>>>(Wq, Wk, Wv);

    cudaFuncSetAttribute(qkv_mma, cudaFuncAttributeMaxDynamicSharedMemorySize,
                         QKV_SMEM);
    qkv_mma<<<128, 256, QKV_SMEM>>>(x, Wq, Wk, Wv);

    cudaFuncSetAttribute(attn5, cudaFuncAttributeMaxDynamicSharedMemorySize,
                         AT_SMEM);
    attn5<<<dim3(32, NB), 256, AT_SMEM>>>(out);
}

// round 17
// speedup vs baseline: 1.4814x; 1.4814x over previous
#include <cuda_runtime.h>
#include <cuda_bf16.h>
#include <cuda_fp16.h>
#include <cstdint>

#define NB 4
#define NT 4096
#define NE 1024
#define HS 64

// Scratch (static device arrays — no allocation)
__device__ float    g_q[NB * NT * HS];
__device__ uint32_t g_kh[NB * NT * 32];      // K fp16x2 pairs along d
__device__ uint32_t g_vth[NB * HS * 2048];   // V^T fp16x2, [b][d][t-pairs]
__device__ uint32_t g_whp[192 * 512];        // W split hi (bf16, for qkv)
__device__ uint32_t g_wlp[192 * 512];        // W split lo

// ---------------------------------------------------------------------------
__device__ __forceinline__ void split2(float a, float b, uint32_t& hi, uint32_t& lo) {
    __nv_bfloat162 h2 = __floats2bfloat162_rn(a, b);
    float2 hf = __bfloat1622float2(h2);
    __nv_bfloat162 l2 = __floats2bfloat162_rn(a - hf.x, b - hf.y);
    hi = *reinterpret_cast<uint32_t*>(&h2);
    lo = *reinterpret_cast<uint32_t*>(&l2);
}

__device__ __forceinline__ uint32_t h2pack(float a, float b) {
    __half2 h = __floats2half2_rn(a, b);
    return *reinterpret_cast<uint32_t*>(&h);
}

// bf16 MMA (qkv)
__device__ __forceinline__ void mma16816(float* c, const uint32_t* a,
                                         uint32_t b0, uint32_t b1) {
    asm volatile(
        "mma.sync.aligned.m16n8k16.row.col.f32.bf16.bf16.f32 "
        "{%0,%1,%2,%3}, {%4,%5,%6,%7}, {%8,%9}, {%0,%1,%2,%3};"
        : "+f"(c[0]), "+f"(c[1]), "+f"(c[2]), "+f"(c[3])
        : "r"(a[0]), "r"(a[1]), "r"(a[2]), "r"(a[3]), "r"(b0), "r"(b1));
}

// fp16 MMA (attention)
__device__ __forceinline__ void mma16816h(float* c, const uint32_t* a,
                                          uint32_t b0, uint32_t b1) {
    asm volatile(
        "mma.sync.aligned.m16n8k16.row.col.f32.f16.f16.f32 "
        "{%0,%1,%2,%3}, {%4,%5,%6,%7}, {%8,%9}, {%0,%1,%2,%3};"
        : "+f"(c[0]), "+f"(c[1]), "+f"(c[2]), "+f"(c[3])
        : "r"(a[0]), "r"(a[1]), "r"(a[2]), "r"(a[3]), "r"(b0), "r"(b1));
}

__device__ __forceinline__ void ldsm4(uint32_t* r, uint32_t addr) {
    asm volatile("ldmatrix.sync.aligned.m8n8.x4.shared.b16 {%0,%1,%2,%3}, [%4];"
                 : "=r"(r[0]), "=r"(r[1]), "=r"(r[2]), "=r"(r[3]) : "r"(addr));
}

__device__ __forceinline__ uint32_t smem_u32(const void* p) {
    uint32_t a;
    asm("{ .reg .u64 t; cvta.to.shared.u64 t, %1; cvt.u32.u64 %0, t; }"
        : "=r"(a) : "l"(p));
    return a;
}

__device__ __forceinline__ void cp16(uint32_t s, const void* g) {
    asm volatile("cp.async.cg.shared.global [%0], [%1], 16;"
                 :: "r"(s), "l"(__cvta_generic_to_global(g)) : "memory");
}

#define ROWB 144   // padded smem row stride — conflict-free ldmatrix

// ===========================================================================
// Stage 0: one-time W split (bf16 hi/lo for the qkv GEMM)
// ===========================================================================
__global__ __launch_bounds__(256) void wprep(
    const float* __restrict__ Wq,
    const float* __restrict__ Wk,
    const float* __restrict__ Wv)
{
    const int row = blockIdx.x;
    const float* W = (row < 64) ? Wq : ((row < 128) ? Wk : Wv);
    const int r = row & 63;
    #pragma unroll
    for (int i = 0; i < 2; i++) {
        const int p = threadIdx.x + i * 256;
        float2 v = *(const float2*)&W[(size_t)r * NE + 2 * p];
        uint32_t hi, lo;
        split2(v.x, v.y, hi, lo);
        g_whp[row * 512 + p] = hi;
        g_wlp[row * 512 + p] = lo;
    }
}

// ===========================================================================
// Stage 1: fused QKV projection (split bf16, 3 passes — precision required).
// Writes Q fp32, K fp16, V^T fp16.  (unchanged from R11/R15)
// ===========================================================================
#define QKV_XH 0
#define QKV_XL 18432
#define QKV_WBASE 36864
#define QKV_WSTG 55296
#define QKV_SMEM (QKV_WBASE + 3 * QKV_WSTG)   // 202752

__global__ __launch_bounds__(256, 1) void qkv_mma(
    const float* __restrict__ x,
    const float* __restrict__ Wq,
    const float* __restrict__ Wk,
    const float* __restrict__ Wv)
{
    extern __shared__ __align__(16) char sm[];
    const uint32_t sb = smem_u32(sm);
    char* Xh = sm + QKV_XH;
    char* Xl = sm + QKV_XL;

    const int tid = threadIdx.x;
    const int wid = tid >> 5;
    const int lane = tid & 31;
    const int g  = lane >> 2;
    const int t3 = lane & 3;
    const int m8 = lane >> 3;
    const int r8 = lane & 7;
    const int rowblk = blockIdx.x * 128;

    const uint32_t lmw = (uint32_t)(((m8 >> 1) * 8 + r8) * ROWB + (m8 & 1) * 16);

    const int xrow = tid >> 1;
    const int xc0  = (tid & 1) * 32;
    const int xob  = xrow * ROWB + xc0 * 2;

    float c[24][4];
    #pragma unroll
    for (int nt = 0; nt < 24; nt++)
        #pragma unroll
        for (int i = 0; i < 4; i++) c[nt][i] = 0.f;

    float4 xr[8];
    {
        const float4* xsrc = (const float4*)&x[(size_t)(rowblk + xrow) * NE + xc0];
        #pragma unroll
        for (int i = 0; i < 8; i++) xr[i] = xsrc[i];
    }

    #pragma unroll
    for (int pc = 0; pc < 2; pc++) {
        const uint32_t wst = sb + QKV_WBASE + pc * QKV_WSTG;
        #pragma unroll
        for (int i = 0; i < 6; i++) {
            const int idx = tid + i * 256;
            const int row = idx >> 3;
            const int off = (idx & 7) * 16;
            cp16(wst + row * ROWB + off,         (const char*)g_whp + row * 2048 + pc * 128 + off);
            cp16(wst + 27648 + row * ROWB + off, (const char*)g_wlp + row * 2048 + pc * 128 + off);
        }
        asm volatile("cp.async.commit_group;" ::: "memory");
    }

    int stg = 0;
    for (int kci = 0; kci < 16; kci++) {
        if (kci < 15)
            asm volatile("cp.async.wait_group 1;" ::: "memory");
        else
            asm volatile("cp.async.wait_group 0;" ::: "memory");
        __syncthreads();

        if (kci + 2 < 16) {
            const int ps = stg + 2 >= 3 ? stg - 1 : stg + 2;
            const uint32_t wst = sb + QKV_WBASE + ps * QKV_WSTG;
            const int kb2 = (kci + 2) * 128;
            #pragma unroll
            for (int i = 0; i < 6; i++) {
                const int idx = tid + i * 256;
                const int row = idx >> 3;
                const int off = (idx & 7) * 16;
                cp16(wst + row * ROWB + off,         (const char*)g_whp + row * 2048 + kb2 + off);
                cp16(wst + 27648 + row * ROWB + off, (const char*)g_wlp + row * 2048 + kb2 + off);
            }
            asm volatile("cp.async.commit_group;" ::: "memory");
        }

        {
            uint32_t hp[16], lp[16];
            #pragma unroll
            for (int i = 0; i < 8; i++) {
                split2(xr[i].x, xr[i].y, hp[2*i],   lp[2*i]);
                split2(xr[i].z, xr[i].w, hp[2*i+1], lp[2*i+1]);
            }
            #pragma unroll
            for (int i = 0; i < 4; i++) {
                *(uint4*)(Xh + xob + 16*i) = make_uint4(hp[4*i], hp[4*i+1], hp[4*i+2], hp[4*i+3]);
                *(uint4*)(Xl + xob + 16*i) = make_uint4(lp[4*i], lp[4*i+1], lp[4*i+2], lp[4*i+3]);
            }
        }
        __syncwarp();

        if (kci + 1 < 16) {
            const float4* xsrc = (const float4*)&x[(size_t)(rowblk + xrow) * NE + (kci + 1) * 64 + xc0];
            #pragma unroll
            for (int i = 0; i < 8; i++) xr[i] = xsrc[i];
        }

        const uint32_t whb = sb + QKV_WBASE + stg * QKV_WSTG;
        const uint32_t wlb = whb + 27648;

        const int rb = (wid * 16 + g) * ROWB;
        #pragma unroll
        for (int ks = 0; ks < 4; ks++) {
            const int colb = ks * 32 + t3 * 4;
            uint32_t ah[4], al[4];
            ah[0] = *(uint32_t*)(Xh + rb + colb);
            ah[1] = *(uint32_t*)(Xh + rb + 8*ROWB + colb);
            ah[2] = *(uint32_t*)(Xh + rb + colb + 16);
            ah[3] = *(uint32_t*)(Xh + rb + 8*ROWB + colb + 16);
            al[0] = *(uint32_t*)(Xl + rb + colb);
            al[1] = *(uint32_t*)(Xl + rb + 8*ROWB + colb);
            al[2] = *(uint32_t*)(Xl + rb + colb + 16);
            al[3] = *(uint32_t*)(Xl + rb + 8*ROWB + colb + 16);
            #pragma unroll
            for (int ntp = 0; ntp < 12; ntp++) {
                uint32_t wh4[4], wl4[4];
                ldsm4(wh4, whb + lmw + ntp * (16 * ROWB) + ks * 32);
                ldsm4(wl4, wlb + lmw + ntp * (16 * ROWB) + ks * 32);
                mma16816(c[2*ntp],   ah, wh4[0], wh4[1]);
                mma16816(c[2*ntp],   ah, wl4[0], wl4[1]);
                mma16816(c[2*ntp],   al, wh4[0], wh4[1]);
                mma16816(c[2*ntp+1], ah, wh4[2], wh4[3]);
                mma16816(c[2*ntp+1], ah, wl4[2], wl4[3]);
                mma16816(c[2*ntp+1], al, wh4[2], wh4[3]);
            }
        }
        stg = (stg + 1 == 3) ? 0 : stg + 1;
    }

    const int r0 = rowblk + wid * 16 + g;
    #pragma unroll
    for (int nt = 0; nt < 8; nt++) {
        const int col = nt * 8 + t3 * 2;
        *(float2*)&g_q[(size_t)r0 * HS + col]       = make_float2(c[nt][0], c[nt][1]);
        *(float2*)&g_q[(size_t)(r0 + 8) * HS + col] = make_float2(c[nt][2], c[nt][3]);
    }
    #pragma unroll
    for (int nt = 8; nt < 16; nt++) {
        const int pidx = (nt - 8) * 4 + t3;
        g_kh[(size_t)r0 * 32 + pidx]       = h2pack(c[nt][0], c[nt][1]);
        g_kh[(size_t)(r0 + 8) * 32 + pidx] = h2pack(c[nt][2], c[nt][3]);
    }

    __syncthreads();
    float* Vs = (float*)sm;
    const int rloc = wid * 16 + g;
    #pragma unroll
    for (int nt = 16; nt < 24; nt++) {
        const int n = nt * 8 + t3 * 2 - 128;
        Vs[n * 132 + rloc]           = c[nt][0];
        Vs[(n + 1) * 132 + rloc]     = c[nt][1];
        Vs[n * 132 + rloc + 8]       = c[nt][2];
        Vs[(n + 1) * 132 + rloc + 8] = c[nt][3];
    }
    __syncthreads();
    {
        const int d  = tid >> 2;
        const int cc = (tid & 3) * 32;
        const int bb = rowblk >> 12;
        const int t0 = rowblk & (NT - 1);
        uint32_t* dh = &g_vth[((size_t)(bb * HS + d)) * 2048 + (t0 + cc) / 2];
        #pragma unroll
        for (int i = 0; i < 8; i++) {
            float4 v = *(float4*)&Vs[d * 132 + cc + 4*i];
            dh[2*i]   = h2pack(v.x, v.y);
            dh[2*i+1] = h2pack(v.z, v.w);
        }
    }
}

// ===========================================================================
// Stage 2: causal flash attention, fp16 HMMA, 128-thread CTAs.
// One 64-row qt per CTA; 4 warps x 16 rows; each warp owns all 64 keys.
// Warp-local softmax (no cross-warp exchange), 1 barrier/iter, 2-3 CTAs/SM.
// ===========================================================================
#define ATSTG 18432                 // stage: KH 9216 | VH 9216
#define AT_QHO (3 * ATSTG)          // 55296
#define AT_SMEM (AT_QHO + 9216)     // 64512

__global__ __launch_bounds__(128) void attn6(float* __restrict__ o)
{
    extern __shared__ __align__(16) char sm[];
    const uint32_t sb = smem_u32(sm);
    const int tid  = threadIdx.x;
    const int lane = tid & 31;
    const int g    = lane >> 2;
    const int t3   = lane & 3;
    const int wq   = tid >> 5;            // warp id 0..3 -> rows wq*16..+15
    const int b    = blockIdx.y;
    const int qt   = 63 - (int)blockIdx.x;   // big tiles launch first
    const int nkt  = qt + 1;
    const int qrow = b * NT + qt * 64;

    const int m8 = lane >> 3;
    const int r8 = lane & 7;
    const uint32_t lmk = (uint32_t)(((m8 >> 1) * 8 + r8) * ROWB + (m8 & 1) * 16);
    const uint32_t lmv = lmk;             // same pattern for V^T (d rows)

    const char* khg = (const char*)g_kh + (size_t)b * NT * 128;
    const char* vhg = (const char*)g_vth + (size_t)b * HS * 8192;

    // ---- stage Q (scaled 1/8, fp16) — warp-local rows ----
    {
        const int r  = tid >> 1;                 // 0..63; warp w writes rows w*16..+15
        const int c0 = (tid & 1) * 32;
        const float4* src = (const float4*)&g_q[(size_t)(qrow + r) * HS + c0];
        uint32_t hp[16];
        #pragma unroll
        for (int i = 0; i < 8; i++) {
            float4 v = src[i];
            hp[2*i]   = h2pack(v.x * 0.125f, v.y * 0.125f);
            hp[2*i+1] = h2pack(v.z * 0.125f, v.w * 0.125f);
        }
        const int ob = r * ROWB + c0 * 2;
        #pragma unroll
        for (int i = 0; i < 4; i++)
            *(uint4*)(sm + AT_QHO + ob + 16*i) =
                make_uint4(hp[4*i], hp[4*i+1], hp[4*i+2], hp[4*i+3]);
    }
    __syncwarp();

    // ---- preload Q fragments ----
    uint32_t qh[4][4];
    {
        const int rb = (wq * 16 + g) * ROWB;
        #pragma unroll
        for (int ks = 0; ks < 4; ks++) {
            const int colb = ks * 32 + t3 * 4;
            qh[ks][0] = *(uint32_t*)(sm + AT_QHO + rb + colb);
            qh[ks][1] = *(uint32_t*)(sm + AT_QHO + rb + 8*ROWB + colb);
            qh[ks][2] = *(uint32_t*)(sm + AT_QHO + rb + colb + 16);
            qh[ks][3] = *(uint32_t*)(sm + AT_QHO + rb + 8*ROWB + colb + 16);
        }
    }

    float oacc[8][4];
    #pragma unroll
    for (int nt = 0; nt < 8; nt++)
        #pragma unroll
        for (int i = 0; i < 4; i++) oacc[nt][i] = 0.f;
    float mi0 = -1e30f, mi1 = -1e30f, li0 = 0.f, li1 = 0.f;

    // ---- prefetch tiles 0 and 1 (128 threads, 8 chunks each/stage) ----
    #pragma unroll 1
    for (int pt = 0; pt < 2; pt++) {
        if (pt < nkt) {
            const uint32_t so = sb + pt * ATSTG;
            #pragma unroll
            for (int i = 0; i < 4; i++) {
                const int idx = tid + i * 128;       // 0..511
                const int kr = idx >> 3;
                const int ko = (idx & 7) * 16;
                cp16(so + kr * ROWB + ko,        khg + (size_t)(pt * 64 + kr) * 128 + ko);
                cp16(so + 9216 + kr * ROWB + ko, vhg + (size_t)kr * 8192 + pt * 128 + ko);
            }
            asm volatile("cp.async.commit_group;" ::: "memory");
        }
    }

    int stg = 0;
    for (int kt = 0; kt < nkt; kt++) {
        if (kt + 1 < nkt)
            asm volatile("cp.async.wait_group 1;" ::: "memory");
        else
            asm volatile("cp.async.wait_group 0;" ::: "memory");
        __syncthreads();   // the ONLY per-iter barrier

        if (kt + 2 < nkt) {
            const int ps = stg + 2 >= 3 ? stg - 1 : stg + 2;
            const int t2 = kt + 2;
            const uint32_t so = sb + ps * ATSTG;
            #pragma unroll
            for (int i = 0; i < 4; i++) {
                const int idx = tid + i * 128;
                const int kr = idx >> 3;
                const int ko = (idx & 7) * 16;
                cp16(so + kr * ROWB + ko,        khg + (size_t)(t2 * 64 + kr) * 128 + ko);
                cp16(so + 9216 + kr * ROWB + ko, vhg + (size_t)kr * 8192 + t2 * 128 + ko);
            }
            asm volatile("cp.async.commit_group;" ::: "memory");
        }

        const uint32_t khb = sb + stg * ATSTG;
        const uint32_t vhb = khb + 9216;

        // ---- S = Q K^T over all 64 keys ----
        float s[8][4];
        #pragma unroll
        for (int nt = 0; nt < 8; nt++)
            #pragma unroll
            for (int i = 0; i < 4; i++) s[nt][i] = 0.f;
        #pragma unroll
        for (int ks = 0; ks < 4; ks++) {
            #pragma unroll
            for (int kb = 0; kb < 4; kb++) {
                uint32_t k4[4];
                ldsm4(k4, khb + lmk + kb * (16 * ROWB) + ks * 32);
                mma16816h(s[2*kb],   qh[ks], k4[0], k4[1]);
                mma16816h(s[2*kb+1], qh[ks], k4[2], k4[3]);
            }
        }

        // ---- causal mask (diag tile) ----
        if (kt == qt) {
            const int lr0 = wq * 16 + g;
            #pragma unroll
            for (int nt = 0; nt < 8; nt++) {
                const int lc = nt * 8 + t3 * 2;
                if (lc > lr0)         s[nt][0] = -1e30f;
                if (lc + 1 > lr0)     s[nt][1] = -1e30f;
                if (lc > lr0 + 8)     s[nt][2] = -1e30f;
                if (lc + 1 > lr0 + 8) s[nt][3] = -1e30f;
            }
        }

        // ---- warp-local online softmax over 64 cols ----
        float m0 = -1e30f, m1 = -1e30f;
        #pragma unroll
        for (int nt = 0; nt < 8; nt++) {
            m0 = fmaxf(m0, fmaxf(s[nt][0], s[nt][1]));
            m1 = fmaxf(m1, fmaxf(s[nt][2], s[nt][3]));
        }
        m0 = fmaxf(m0, __shfl_xor_sync(0xffffffffu, m0, 1));
        m0 = fmaxf(m0, __shfl_xor_sync(0xffffffffu, m0, 2));
        m1 = fmaxf(m1, __shfl_xor_sync(0xffffffffu, m1, 1));
        m1 = fmaxf(m1, __shfl_xor_sync(0xffffffffu, m1, 2));

        const float mn0 = fmaxf(mi0, m0);
        const float mn1 = fmaxf(mi1, m1);
        const float corr0 = __expf(mi0 - mn0);
        const float corr1 = __expf(mi1 - mn1);

        float sum0 = 0.f, sum1 = 0.f;
        #pragma unroll
        for (int nt = 0; nt < 8; nt++) {
            s[nt][0] = __expf(s[nt][0] - mn0);
            s[nt][1] = __expf(s[nt][1] - mn0);
            s[nt][2] = __expf(s[nt][2] - mn1);
            s[nt][3] = __expf(s[nt][3] - mn1);
            sum0 += s[nt][0] + s[nt][1];
            sum1 += s[nt][2] + s[nt][3];
        }
        sum0 += __shfl_xor_sync(0xffffffffu, sum0, 1);
        sum0 += __shfl_xor_sync(0xffffffffu, sum0, 2);
        sum1 += __shfl_xor_sync(0xffffffffu, sum1, 1);
        sum1 += __shfl_xor_sync(0xffffffffu, sum1, 2);

        li0 = li0 * corr0 + sum0;  mi0 = mn0;
        li1 = li1 * corr1 + sum1;  mi1 = mn1;

        #pragma unroll
        for (int nt = 0; nt < 8; nt++) {
            oacc[nt][0] *= corr0;  oacc[nt][1] *= corr0;
            oacc[nt][2] *= corr1;  oacc[nt][3] *= corr1;
        }

        // ---- O += P V over 4 k-steps of 16 keys ----
        #pragma unroll
        for (int k2 = 0; k2 < 4; k2++) {
            uint32_t pah[4];
            pah[0] = h2pack(s[2*k2][0],   s[2*k2][1]);
            pah[1] = h2pack(s[2*k2][2],   s[2*k2][3]);
            pah[2] = h2pack(s[2*k2+1][0], s[2*k2+1][1]);
            pah[3] = h2pack(s[2*k2+1][2], s[2*k2+1][3]);
            #pragma unroll
            for (int dt = 0; dt < 4; dt++) {
                uint32_t vh4[4];
                ldsm4(vh4, vhb + dt * (16 * ROWB) + lmv + k2 * 32);
                mma16816h(oacc[2*dt],   pah, vh4[0], vh4[1]);
                mma16816h(oacc[2*dt+1], pah, vh4[2], vh4[3]);
            }
        }
        stg = (stg + 1 == 3) ? 0 : stg + 1;
    }

    // ---- epilogue: warp-owned rows, direct store ----
    const float inv0 = 1.0f / li0;
    const float inv1 = 1.0f / li1;
    const int rowA = qrow + wq * 16 + g;
    #pragma unroll
    for (int nt = 0; nt < 8; nt++) {
        const int col = nt * 8 + t3 * 2;
        *(float2*)&o[(size_t)rowA * HS + col] =
            make_float2(oacc[nt][0] * inv0, oacc[nt][1] * inv0);
        *(float2*)&o[(size_t)(rowA + 8) * HS + col] =
            make_float2(oacc[nt][2] * inv1, oacc[nt][3] * inv1);
    }
}

// ===========================================================================
extern "C" void kernel_launch(void* const* d_in, const int* in_sizes, int n_in,
                              void* d_out, int out_size)
{
    const float* x  = (const float*)d_in[0];
    const float* Wq = (const float*)d_in[1];
    const float* Wk = (const float*)d_in[2];
    const float* Wv = (const float*)d_in[3];
    float* out = (float*)d_out;
    (void)in_sizes; (void)n_in; (void)out_size;

    wprep<<<192, 256>>>(Wq, Wk, Wv);

    cudaFuncSetAttribute(qkv_mma, cudaFuncAttributeMaxDynamicSharedMemorySize,
                         QKV_SMEM);
    qkv_mma<<<128, 256, QKV_SMEM>>>(x, Wq, Wk, Wv);

    cudaFuncSetAttribute(attn6, cudaFuncAttributeMaxDynamicSharedMemorySize,
                         AT_SMEM);
    attn6<<<dim3(64, NB), 128, AT_SMEM>>>(out);
}